// round 2
// baseline (speedup 1.0000x reference)
#include <cuda_runtime.h>
#include <math.h>

#define LSEQ   1024
#define DMODEL 1024
#define DINNER 2048
#define NSTATE 16
#define DTRANK 64
#define XDBLC  96     // dt_rank + 2*N = 64 + 32

// ---------------- scratch (device globals; no allocation allowed) ----------
__device__ float g_xr   [LSEQ * 2 * DINNER];   // [L, 4096]  x@W_in (x_in | res)
__device__ float g_xconv[LSEQ * DINNER];       // [L, 2048]  silu(conv(x_in))
__device__ float g_xdbl [LSEQ * XDBLC];        // [L, 96]    dt|B|C
__device__ float g_delta[LSEQ * DINNER];       // [L, 2048]
__device__ float g_z    [LSEQ * DINNER];       // [L, 2048]  y * silu(res)

__device__ __forceinline__ float siluf(float x)     { return x / (1.0f + expf(-x)); }
__device__ __forceinline__ float softplusf(float x) { return x > 20.0f ? x : log1pf(expf(x)); }

// ---------------- generic tiled fp32 GEMM ----------------------------------
// C[M,N] = A[M,K](lda) * B[K,N](ldb), row-major.
// MODE 0: plain store. MODE 1: store softplus(acc + bias[col]). MODE 2: atomicAdd (split-K via blockIdx.z).
template<int BM,int BN,int BK,int TM,int TN,int MODE>
__global__ void gemm_kernel(int M,int N,int K,
                            const float* __restrict__ A,int lda,
                            const float* __restrict__ B,int ldb,
                            float* __restrict__ C,int ldc,
                            const float* __restrict__ bias,int kChunk)
{
    constexpr int THREADS = (BM/TM)*(BN/TN);
    __shared__ float As[BK][BM];
    __shared__ float Bs[BK][BN];

    const int tid  = threadIdx.x;
    const int tcol = tid % (BN/TN);
    const int trow = tid / (BN/TN);
    const int rowBase = blockIdx.y * BM;
    const int colBase = blockIdx.x * BN;

    int k0 = 0, kEnd = K;
    if (MODE == 2) { k0 = blockIdx.z * kChunk; kEnd = min(K, k0 + kChunk); }

    float acc[TM][TN];
    #pragma unroll
    for (int i=0;i<TM;i++)
        #pragma unroll
        for (int j=0;j<TN;j++) acc[i][j] = 0.0f;

    for (; k0 < kEnd; k0 += BK) {
        // load A tile BM x BK
        for (int i = tid; i < BM*BK; i += THREADS) {
            int r = i / BK, c = i % BK;
            int gr = rowBase + r, gc = k0 + c;
            As[c][r] = (gr < M && gc < K) ? A[(long)gr*lda + gc] : 0.0f;
        }
        // load B tile BK x BN
        for (int i = tid; i < BK*BN; i += THREADS) {
            int r = i / BN, c = i % BN;
            int gr = k0 + r, gc = colBase + c;
            Bs[r][c] = (gr < K && gc < N) ? B[(long)gr*ldb + gc] : 0.0f;
        }
        __syncthreads();

        #pragma unroll
        for (int k=0;k<BK;k++) {
            float a[TM], b[TN];
            #pragma unroll
            for (int i=0;i<TM;i++) a[i] = As[k][trow*TM + i];
            #pragma unroll
            for (int j=0;j<TN;j++) b[j] = Bs[k][tcol*TN + j];
            #pragma unroll
            for (int i=0;i<TM;i++)
                #pragma unroll
                for (int j=0;j<TN;j++)
                    acc[i][j] += a[i]*b[j];
        }
        __syncthreads();
    }

    #pragma unroll
    for (int i=0;i<TM;i++) {
        int gr = rowBase + trow*TM + i;
        if (gr >= M) continue;
        #pragma unroll
        for (int j=0;j<TN;j++) {
            int gc = colBase + tcol*TN + j;
            if (gc >= N) continue;
            float v = acc[i][j];
            if (MODE == 1) { v = softplusf(v + bias[gc]); }
            if (MODE == 2) { atomicAdd(&C[(long)gr*ldc + gc], v); }
            else           { C[(long)gr*ldc + gc] = v; }
        }
    }
}

// ---------------- zero small buffer -----------------------------------------
__global__ void zero_kernel(float* p, int n)
{
    int i = blockIdx.x*blockDim.x + threadIdx.x;
    if (i < n) p[i] = 0.0f;
}

// ---------------- causal depthwise conv (K=4) + SiLU ------------------------
__global__ void conv_silu_kernel(const float* __restrict__ conv_w,
                                 const float* __restrict__ conv_b)
{
    int idx = blockIdx.x*blockDim.x + threadIdx.x;   // [0, L*DINNER)
    if (idx >= LSEQ*DINNER) return;
    int d = idx & (DINNER-1);
    int l = idx >> 11;                               // DINNER = 2^11
    float acc = conv_b[d];
    #pragma unroll
    for (int k = 0; k < 4; k++) {
        int ls = l - 3 + k;
        if (ls >= 0) acc += g_xr[(long)ls * (2*DINNER) + d] * conv_w[d*4 + k];
    }
    g_xconv[(long)l*DINNER + d] = siluf(acc);
}

// ---------------- selective scan ---------------------------------------------
// One 16-lane group per channel d; lane n owns state h[d,n]. Two channels/warp.
__global__ void scan_kernel(const float* __restrict__ A_log,
                            const float* __restrict__ Dvec)
{
    int gtid   = blockIdx.x*blockDim.x + threadIdx.x;
    int warpId = gtid >> 5;
    int lane   = threadIdx.x & 31;
    int grp    = lane >> 4;          // 0/1: which channel in this warp
    int n      = lane & 15;          // state index
    int d      = warpId*2 + grp;
    if (d >= DINNER) return;

    const float Adn = -expf(A_log[d*NSTATE + n]);
    const float Dd  = Dvec[d];
    float h = 0.0f;

    for (int l = 0; l < LSEQ; l++) {
        float dl = g_delta[(long)l*DINNER + d];
        float u  = g_xconv[(long)l*DINNER + d];
        float Bv = g_xdbl[l*XDBLC + DTRANK + n];
        float Cv = g_xdbl[l*XDBLC + DTRANK + NSTATE + n];

        h = expf(dl * Adn) * h + dl * Bv * u;

        float c = h * Cv;
        c += __shfl_xor_sync(0xffffffffu, c, 8);
        c += __shfl_xor_sync(0xffffffffu, c, 4);
        c += __shfl_xor_sync(0xffffffffu, c, 2);
        c += __shfl_xor_sync(0xffffffffu, c, 1);

        if (n == 0) {
            float y = c + u * Dd;
            float r = g_xr[(long)l*(2*DINNER) + DINNER + d];   // res
            g_z[(long)l*DINNER + d] = y * siluf(r);
        }
    }
}

// ---------------- launch ------------------------------------------------------
extern "C" void kernel_launch(void* const* d_in, const int* in_sizes, int n_in,
                              void* d_out, int out_size)
{
    const float* x      = (const float*)d_in[0];
    const float* W_in   = (const float*)d_in[1];
    const float* conv_w = (const float*)d_in[2];
    const float* conv_b = (const float*)d_in[3];
    const float* W_x    = (const float*)d_in[4];
    const float* W_dt   = (const float*)d_in[5];
    const float* b_dt   = (const float*)d_in[6];
    const float* A_log  = (const float*)d_in[7];
    const float* Dv     = (const float*)d_in[8];
    const float* W_out  = (const float*)d_in[9];
    float* out = (float*)d_out;

    float *xr, *xconv, *xdbl, *delta, *z;
    cudaGetSymbolAddress((void**)&xr,    g_xr);
    cudaGetSymbolAddress((void**)&xconv, g_xconv);
    cudaGetSymbolAddress((void**)&xdbl,  g_xdbl);
    cudaGetSymbolAddress((void**)&delta, g_delta);
    cudaGetSymbolAddress((void**)&z,     g_z);

    // 1) x [1024,1024] @ W_in [1024,4096] -> xr [1024,4096]
    gemm_kernel<128,128,8,8,8,0><<<dim3(4096/128, 1024/128), 256>>>(
        1024, 4096, 1024, x, 1024, W_in, 4096, xr, 4096, nullptr, 0);

    // 2) causal depthwise conv + SiLU -> xconv [1024,2048]
    conv_silu_kernel<<<(LSEQ*DINNER)/256, 256>>>(conv_w, conv_b);

    // 3) xconv [1024,2048] @ W_x [2048,96] -> xdbl [1024,96]   (split-K x8)
    zero_kernel<<<(LSEQ*XDBLC + 255)/256, 256>>>(xdbl, LSEQ*XDBLC);
    gemm_kernel<64,32,16,4,4,2><<<dim3(3, 1024/64, 8), 128>>>(
        1024, XDBLC, 2048, xconv, 2048, W_x, XDBLC, xdbl, XDBLC, nullptr, 256);

    // 4) dt [1024,64](lda=96) @ W_dt [64,2048] + b_dt, softplus -> delta
    gemm_kernel<128,128,8,8,8,1><<<dim3(2048/128, 1024/128), 256>>>(
        1024, 2048, 64, xdbl, XDBLC, W_dt, 2048, delta, 2048, b_dt, 0);

    // 5) selective scan + gating -> z [1024,2048]
    //    2048 channels, 2 per warp -> 1024 warps, 128 threads/block -> 256 blocks
    scan_kernel<<<256, 128>>>(A_log, Dv);

    // 6) z [1024,2048] @ W_out [2048,1024] -> out [1024,1024]
    gemm_kernel<128,64,8,8,4,0><<<dim3(1024/64, 1024/128), 256>>>(
        1024, 1024, 2048, z, 2048, W_out, 1024, out, 1024, nullptr, 0);
}

// round 6
// speedup vs baseline: 2.6214x; 2.6214x over previous
#include <cuda_runtime.h>
#include <cuda_bf16.h>
#include <math.h>
#include <stdint.h>

#define LSEQ   1024
#define DMODEL 1024
#define DINNER 2048
#define NSTATE 16
#define DTRANK 64
#define XDBLC  96     // dt_rank + 2*N = 64 + 32

// ---------------- scratch (device globals; no allocation allowed) ----------
__device__ float g_xr   [LSEQ * 2 * DINNER];   // [L, 4096]  x@W_in (x_in | res)
__device__ float g_xconv[LSEQ * DINNER];       // [L, 2048]  silu(conv(x_in))
__device__ float g_xdbl [LSEQ * XDBLC];        // [L, 96]    dt|B|C
__device__ float g_delta[LSEQ * DINNER];       // [L, 2048]
__device__ float g_z    [LSEQ * DINNER];       // [L, 2048]  y * silu(res)

__device__ __forceinline__ float siluf(float x)     { return x / (1.0f + __expf(-x)); }
__device__ __forceinline__ float softplusf(float x) { return x > 20.0f ? x : log1pf(expf(x)); }

// ---------------- warp-level bf16 MMA (sm_80+ baseline feature) -------------
__device__ __forceinline__ void mma16816(float c[4],
                                         uint32_t a0, uint32_t a1, uint32_t a2, uint32_t a3,
                                         uint32_t b0, uint32_t b1) {
    asm volatile(
        "mma.sync.aligned.m16n8k16.row.col.f32.bf16.bf16.f32 "
        "{%0,%1,%2,%3}, {%4,%5,%6,%7}, {%8,%9}, {%0,%1,%2,%3};"
        : "+f"(c[0]), "+f"(c[1]), "+f"(c[2]), "+f"(c[3])
        : "r"(a0), "r"(a1), "r"(a2), "r"(a3), "r"(b0), "r"(b1));
}

// ======================= bf16-split MMA GEMM ================================
// C[M,N] = A[M,K] * B[K,N], fp32 in/out, fp32 accumulation on tensor cores.
// fp32 operands split to bf16 hi+lo; 3 cross products -> ~2^-17 rel accuracy.
// MODE 0: plain store. MODE 1: softplus(acc + bias[col]). MODE 2: atomicAdd (split-K via blockIdx.z).
// Block: 256 thr (8 warps), tile BM=128 x BN, BK=32. Warp grid 4(M) x 2(N).
template<int BN, int MODE>
__global__ __launch_bounds__(256, 1) void gemm_mma(
    int M, int N, int K,
    const float* __restrict__ A, int lda,
    const float* __restrict__ B, int ldb,
    float* __restrict__ C, int ldc,
    const float* __restrict__ bias, int kChunk)
{
    constexpr int BM = 128, BK = 32;
    constexpr int AST = 36;                 // A smem row stride (bf16 elems), conflict-free
    constexpr int BST = 36;                 // B smem (transposed) row stride
    constexpr int WN  = BN / 2;             // warp tile N
    constexpr int NT  = WN / 8;             // n-tiles per warp
    constexpr int A_ELE = BM * AST;         // 4608
    constexpr int B_ELE = BN * BST;
    constexpr int STAGE = 2 * A_ELE + 2 * B_ELE;   // Ah|Al|Bh|Bl per stage
    constexpr int NBLD  = (BK * BN) / 256;  // B floats per thread per chunk

    extern __shared__ __nv_bfloat16 sm[];

    const int tid  = threadIdx.x;
    const int lane = tid & 31;
    const int wid  = tid >> 5;
    const int warpM = wid >> 1;             // 0..3  (32 rows each)
    const int warpN = wid & 1;              // 0..1  (WN cols each)
    const int rowBase = blockIdx.y * BM;
    const int colBase = blockIdx.x * BN;

    int k0 = 0, kEnd = K;
    if (MODE == 2) { k0 = blockIdx.z * kChunk; kEnd = k0 + kChunk; }
    const int nch = (kEnd - k0) / BK;

    float acc[2][NT][4];
    #pragma unroll
    for (int mt = 0; mt < 2; mt++)
        #pragma unroll
        for (int nt = 0; nt < NT; nt++)
            #pragma unroll
            for (int j = 0; j < 4; j++) acc[mt][nt][j] = 0.0f;

    float4 aReg[4];
    float  bReg[NBLD];

    // ---- global loads into registers for chunk ch
    auto loadG = [&](int ch) {
        const int kk = k0 + ch * BK;
        #pragma unroll
        for (int j = 0; j < 4; j++) {
            int idx = tid + j * 256;        // 0..1023 over BM*BK/4 float4s
            int r = idx >> 3, c4 = idx & 7;
            aReg[j] = *reinterpret_cast<const float4*>(&A[(rowBase + r) * lda + kk + c4 * 4]);
        }
        #pragma unroll
        for (int i = 0; i < NBLD; i++) {
            int e = tid + i * 256;
            int kb = e / BN, n = e - kb * BN;
            bReg[i] = B[(kk + kb) * ldb + colBase + n];
        }
    };

    // ---- registers -> smem stage s (bf16 hi/lo split; B transposed [n][k])
    auto storeS = [&](int s) {
        __nv_bfloat16* Ah = sm + s * STAGE;
        __nv_bfloat16* Al = Ah + A_ELE;
        __nv_bfloat16* Bh = Al + A_ELE;
        __nv_bfloat16* Bl = Bh + B_ELE;
        #pragma unroll
        for (int j = 0; j < 4; j++) {
            int idx = tid + j * 256;
            int r = idx >> 3, c = (idx & 7) * 4;
            float4 v = aReg[j];
            __nv_bfloat162 h01, h23, l01, l23;
            h01.x = __float2bfloat16(v.x); l01.x = __float2bfloat16(v.x - __bfloat162float(h01.x));
            h01.y = __float2bfloat16(v.y); l01.y = __float2bfloat16(v.y - __bfloat162float(h01.y));
            h23.x = __float2bfloat16(v.z); l23.x = __float2bfloat16(v.z - __bfloat162float(h23.x));
            h23.y = __float2bfloat16(v.w); l23.y = __float2bfloat16(v.w - __bfloat162float(h23.y));
            uint2 uh, ul;
            uh.x = reinterpret_cast<uint32_t&>(h01); uh.y = reinterpret_cast<uint32_t&>(h23);
            ul.x = reinterpret_cast<uint32_t&>(l01); ul.y = reinterpret_cast<uint32_t&>(l23);
            *reinterpret_cast<uint2*>(&Ah[r * AST + c]) = uh;
            *reinterpret_cast<uint2*>(&Al[r * AST + c]) = ul;
        }
        #pragma unroll
        for (int i = 0; i < NBLD; i++) {
            int e = tid + i * 256;
            int kb = e / BN, n = e - kb * BN;
            float v = bReg[i];
            __nv_bfloat16 h = __float2bfloat16(v);
            Bh[n * BST + kb] = h;
            Bl[n * BST + kb] = __float2bfloat16(v - __bfloat162float(h));
        }
    };

    // ---- tensor-core compute on smem stage s
    auto compute = [&](int s) {
        const __nv_bfloat16* Ah = sm + s * STAGE;
        const __nv_bfloat16* Al = Ah + A_ELE;
        const __nv_bfloat16* Bh = Al + A_ELE;
        const __nv_bfloat16* Bl = Bh + B_ELE;
        #pragma unroll
        for (int ks = 0; ks < 2; ks++) {
            const int kc = ks * 16 + (lane & 3) * 2;
            uint32_t ah[2][4], al[2][4];
            #pragma unroll
            for (int mt = 0; mt < 2; mt++) {
                int r = warpM * 32 + mt * 16 + (lane >> 2);
                ah[mt][0] = *reinterpret_cast<const uint32_t*>(&Ah[ r      * AST + kc    ]);
                ah[mt][1] = *reinterpret_cast<const uint32_t*>(&Ah[(r + 8) * AST + kc    ]);
                ah[mt][2] = *reinterpret_cast<const uint32_t*>(&Ah[ r      * AST + kc + 8]);
                ah[mt][3] = *reinterpret_cast<const uint32_t*>(&Ah[(r + 8) * AST + kc + 8]);
                al[mt][0] = *reinterpret_cast<const uint32_t*>(&Al[ r      * AST + kc    ]);
                al[mt][1] = *reinterpret_cast<const uint32_t*>(&Al[(r + 8) * AST + kc    ]);
                al[mt][2] = *reinterpret_cast<const uint32_t*>(&Al[ r      * AST + kc + 8]);
                al[mt][3] = *reinterpret_cast<const uint32_t*>(&Al[(r + 8) * AST + kc + 8]);
            }
            #pragma unroll
            for (int nt = 0; nt < NT; nt++) {
                int n = warpN * WN + nt * 8 + (lane >> 2);
                uint32_t bh0 = *reinterpret_cast<const uint32_t*>(&Bh[n * BST + kc    ]);
                uint32_t bh1 = *reinterpret_cast<const uint32_t*>(&Bh[n * BST + kc + 8]);
                uint32_t bl0 = *reinterpret_cast<const uint32_t*>(&Bl[n * BST + kc    ]);
                uint32_t bl1 = *reinterpret_cast<const uint32_t*>(&Bl[n * BST + kc + 8]);
                #pragma unroll
                for (int mt = 0; mt < 2; mt++) {
                    mma16816(acc[mt][nt], ah[mt][0], ah[mt][1], ah[mt][2], ah[mt][3], bh0, bh1);
                    mma16816(acc[mt][nt], al[mt][0], al[mt][1], al[mt][2], al[mt][3], bh0, bh1);
                    mma16816(acc[mt][nt], ah[mt][0], ah[mt][1], ah[mt][2], ah[mt][3], bl0, bl1);
                }
            }
        }
    };

    // ---- software-pipelined mainloop (double-buffered smem)
    loadG(0);
    storeS(0);
    __syncthreads();
    for (int ch = 0; ch < nch; ch++) {
        if (ch + 1 < nch) loadG(ch + 1);
        compute(ch & 1);
        if (ch + 1 < nch) storeS((ch + 1) & 1);
        __syncthreads();
    }

    // ---- epilogue straight from accumulators (coalesced within quads)
    #pragma unroll
    for (int mt = 0; mt < 2; mt++) {
        #pragma unroll
        for (int nt = 0; nt < NT; nt++) {
            int row = rowBase + warpM * 32 + mt * 16 + (lane >> 2);
            int col = colBase + warpN * WN + nt * 8 + (lane & 3) * 2;
            float v0 = acc[mt][nt][0], v1 = acc[mt][nt][1];
            float v2 = acc[mt][nt][2], v3 = acc[mt][nt][3];
            if (MODE == 1) {
                v0 = softplusf(v0 + bias[col]); v1 = softplusf(v1 + bias[col + 1]);
                v2 = softplusf(v2 + bias[col]); v3 = softplusf(v3 + bias[col + 1]);
            }
            if (MODE == 2) {
                atomicAdd(&C[ row      * ldc + col    ], v0);
                atomicAdd(&C[ row      * ldc + col + 1], v1);
                atomicAdd(&C[(row + 8) * ldc + col    ], v2);
                atomicAdd(&C[(row + 8) * ldc + col + 1], v3);
            } else {
                float2 p0; p0.x = v0; p0.y = v1;
                float2 p1; p1.x = v2; p1.y = v3;
                *reinterpret_cast<float2*>(&C[ row      * ldc + col]) = p0;
                *reinterpret_cast<float2*>(&C[(row + 8) * ldc + col]) = p1;
            }
        }
    }
}

// ---------------- zero small buffer -----------------------------------------
__global__ void zero_kernel(float* p, int n)
{
    int i = blockIdx.x * blockDim.x + threadIdx.x;
    if (i < n) p[i] = 0.0f;
}

// ---------------- causal depthwise conv (K=4) + SiLU ------------------------
__global__ void conv_silu_kernel(const float* __restrict__ conv_w,
                                 const float* __restrict__ conv_b)
{
    int idx = blockIdx.x * blockDim.x + threadIdx.x;
    if (idx >= LSEQ * DINNER) return;
    int d = idx & (DINNER - 1);
    int l = idx >> 11;
    float acc = conv_b[d];
    #pragma unroll
    for (int k = 0; k < 4; k++) {
        int ls = l - 3 + k;
        if (ls >= 0) acc += g_xr[(long)ls * (2 * DINNER) + d] * conv_w[d * 4 + k];
    }
    g_xconv[(long)l * DINNER + d] = siluf(acc);
}

// ---------------- selective scan ---------------------------------------------
// One 16-lane group per channel d; lane n owns state h[d,n]. Two channels/warp.
// Software-pipelined loads so the serial critical path is one FFMA.
__global__ void scan_kernel(const float* __restrict__ A_log,
                            const float* __restrict__ Dvec)
{
    int gtid   = blockIdx.x * blockDim.x + threadIdx.x;
    int warpId = gtid >> 5;
    int lane   = threadIdx.x & 31;
    int grp    = lane >> 4;
    int n      = lane & 15;
    int d      = warpId * 2 + grp;
    if (d >= DINNER) return;

    const float Adn = -expf(A_log[d * NSTATE + n]);
    const float Dd  = Dvec[d];

    const float* pD = g_delta + d;
    const float* pU = g_xconv + d;
    const float* pB = g_xdbl + DTRANK + n;
    const float* pC = g_xdbl + DTRANK + NSTATE + n;
    const float* pR = g_xr + DINNER + d;
    float*       pZ = g_z + d;

    float h = 0.0f;
    float dl = pD[0], u = pU[0], Bv = pB[0], Cv = pC[0];

    for (int l = 0; l < LSEQ; l++) {
        float dl2 = 0.f, u2 = 0.f, B2 = 0.f, C2 = 0.f;
        if (l + 1 < LSEQ) {
            dl2 = pD[(l + 1) * DINNER];
            u2  = pU[(l + 1) * DINNER];
            B2  = pB[(l + 1) * XDBLC];
            C2  = pC[(l + 1) * XDBLC];
        }
        float e = __expf(dl * Adn);
        h = fmaf(e, h, dl * Bv * u);

        float c = h * Cv;
        c += __shfl_xor_sync(0xffffffffu, c, 8);
        c += __shfl_xor_sync(0xffffffffu, c, 4);
        c += __shfl_xor_sync(0xffffffffu, c, 2);
        c += __shfl_xor_sync(0xffffffffu, c, 1);

        if (n == 0) {
            float y = fmaf(u, Dd, c);
            float r = pR[l * 2 * DINNER];
            pZ[l * DINNER] = y * siluf(r);
        }
        dl = dl2; u = u2; Bv = B2; Cv = C2;
    }
}

// ---------------- launch ------------------------------------------------------
extern "C" void kernel_launch(void* const* d_in, const int* in_sizes, int n_in,
                              void* d_out, int out_size)
{
    const float* x      = (const float*)d_in[0];
    const float* W_in   = (const float*)d_in[1];
    const float* conv_w = (const float*)d_in[2];
    const float* conv_b = (const float*)d_in[3];
    const float* W_x    = (const float*)d_in[4];
    const float* W_dt   = (const float*)d_in[5];
    const float* b_dt   = (const float*)d_in[6];
    const float* A_log  = (const float*)d_in[7];
    const float* Dv     = (const float*)d_in[8];
    const float* W_out  = (const float*)d_in[9];
    float* out = (float*)d_out;

    float *xr, *xconv, *xdbl, *delta, *z;
    cudaGetSymbolAddress((void**)&xr,    g_xr);
    cudaGetSymbolAddress((void**)&xconv, g_xconv);
    cudaGetSymbolAddress((void**)&xdbl,  g_xdbl);
    cudaGetSymbolAddress((void**)&delta, g_delta);
    cudaGetSymbolAddress((void**)&z,     g_z);

    // dynamic smem bytes: 2 stages * (2*128*36 + 2*BN*36) bf16 elems * 2B
    const int SMEM_128 = 2 * (2 * 128 * 36 + 2 * 128 * 36) * 2;  // 73728
    const int SMEM_96  = 2 * (2 * 128 * 36 + 2 *  96 * 36) * 2;  // 64512
    const int SMEM_64  = 2 * (2 * 128 * 36 + 2 *  64 * 36) * 2;  // 55296
    cudaFuncSetAttribute(gemm_mma<128, 0>, cudaFuncAttributeMaxDynamicSharedMemorySize, SMEM_128);
    cudaFuncSetAttribute(gemm_mma<128, 1>, cudaFuncAttributeMaxDynamicSharedMemorySize, SMEM_128);
    cudaFuncSetAttribute(gemm_mma<96, 2>,  cudaFuncAttributeMaxDynamicSharedMemorySize, SMEM_96);
    cudaFuncSetAttribute(gemm_mma<64, 0>,  cudaFuncAttributeMaxDynamicSharedMemorySize, SMEM_64);

    // 1) x [1024,1024] @ W_in [1024,4096] -> xr [1024,4096]
    gemm_mma<128, 0><<<dim3(4096 / 128, 1024 / 128), 256, SMEM_128>>>(
        1024, 4096, 1024, x, 1024, W_in, 4096, xr, 4096, nullptr, 0);

    // 2) causal depthwise conv + SiLU -> xconv [1024,2048]
    conv_silu_kernel<<<(LSEQ * DINNER) / 256, 256>>>(conv_w, conv_b);

    // 3) xconv [1024,2048] @ W_x [2048,96] -> xdbl [1024,96]   (split-K x8, atomic)
    zero_kernel<<<(LSEQ * XDBLC + 255) / 256, 256>>>(xdbl, LSEQ * XDBLC);
    gemm_mma<96, 2><<<dim3(1, 1024 / 128, 8), 256, SMEM_96>>>(
        1024, XDBLC, 2048, xconv, 2048, W_x, XDBLC, xdbl, XDBLC, nullptr, 256);

    // 4) dt [1024,64](lda=96) @ W_dt [64,2048] + b_dt, softplus -> delta
    gemm_mma<128, 1><<<dim3(2048 / 128, 1024 / 128), 256, SMEM_128>>>(
        1024, 2048, 64, xdbl, XDBLC, W_dt, 2048, delta, 2048, b_dt, 0);

    // 5) selective scan + gating -> z [1024,2048]
    scan_kernel<<<256, 128>>>(A_log, Dv);

    // 6) z [1024,2048] @ W_out [2048,1024] -> out [1024,1024]  (BN=64 -> 128 CTAs)
    gemm_mma<64, 0><<<dim3(1024 / 64, 1024 / 128), 256, SMEM_64>>>(
        1024, 1024, 2048, z, 2048, W_out, 1024, out, 1024, nullptr, 0);
}